// round 7
// baseline (speedup 1.0000x reference)
#include <cuda_runtime.h>
#include <cuda_bf16.h>
#include <cstdint>

#define N_SYSTEMS 16
#define D 64
#define NWARPS 4
#define THREADS 128
#define NBLOCKS 740          // 148 SMs * 5 CTAs (41 KB smem each)
#define STAGES 3
#define CHUNK_ROWS 32
#define ROW_BYTES (D * 4)                  // 256 B
#define CHUNK_BYTES (CHUNK_ROWS * ROW_BYTES)  // 8192 B

// Global scratch. Zero-initialized at module load; the last block re-zeroes
// after consuming it, so the "zero at entry" invariant holds across graph
// replays without a dedicated zeroing launch.
__device__ float g_sums[N_SYSTEMS * D];
__device__ float g_counts[N_SYSTEMS];
__device__ unsigned int g_ticket;   // zero-init; reset by last block

__device__ __forceinline__ uint32_t smem_u32(const void* p) {
    return (uint32_t)__cvta_generic_to_shared(p);
}

__device__ __forceinline__ void mbar_init(uint32_t mb, uint32_t count) {
    asm volatile("mbarrier.init.shared.b64 [%0], %1;" :: "r"(mb), "r"(count) : "memory");
}

__device__ __forceinline__ void mbar_expect_tx(uint32_t mb, uint32_t bytes) {
    asm volatile("mbarrier.arrive.expect_tx.shared.b64 _, [%0], %1;"
                 :: "r"(mb), "r"(bytes) : "memory");
}

__device__ __forceinline__ void bulk_ldgsts(uint32_t dst_smem, const void* src, uint32_t bytes,
                                            uint32_t mb) {
    asm volatile(
        "cp.async.bulk.shared::cluster.global.mbarrier::complete_tx::bytes [%0], [%1], %2, [%3];"
        :: "r"(dst_smem), "l"(src), "r"(bytes), "r"(mb) : "memory");
}

__device__ __forceinline__ void mbar_wait(uint32_t mb, int phase) {
    asm volatile(
        "{\n\t"
        ".reg .pred P1;\n\t"
        "WAIT_LOOP_%=:\n\t"
        "mbarrier.try_wait.parity.acquire.cta.shared::cta.b64 P1, [%0], %1, 0x989680;\n\t"
        "@P1 bra.uni WAIT_DONE_%=;\n\t"
        "bra.uni WAIT_LOOP_%=;\n\t"
        "WAIT_DONE_%=:\n\t"
        "}"
        :: "r"(mb), "r"(phase) : "memory");
}

// TMA-pipelined streaming segment-sum.
// Each CTA streams 8KB chunks (32 rows) gmem->smem via cp.async.bulk with a
// 3-stage mbarrier ring. Warp w processes rows [8w, 8w+8) of each chunk as 4
// pairs (lanes 0-15 = even row, 16-31 = odd row). Per-warp private shared
// accumulators; last block computes the 16x16 epilogue.
__global__ void __launch_bounds__(THREADS, 5) accumulate_kernel(
    const float* __restrict__ out, const int* __restrict__ system,
    float* __restrict__ dist, int n_rows)
{
    __shared__ float4 ssum4[NWARPS][N_SYSTEMS][16];   // 16 KB
    __shared__ float  scount[NWARPS][N_SYSTEMS];      // 256 B
    __shared__ __align__(16) float buf[STAGES][CHUNK_BYTES / 4];  // 24 KB
    __shared__ __align__(8) unsigned long long mbar[STAGES];
    __shared__ int s_last;

    const int tid  = threadIdx.x;
    const int lane = tid & 31;
    const int warp = tid >> 5;
    const int half = lane >> 4;      // which row of the pair
    const int q    = lane & 15;      // float4 index within row
    const int w8   = warp * 8;       // first local row this warp owns

    const long long nchunks = (long long)n_rows / CHUNK_ROWS;

    // Zero private accumulators; init barriers; issue prologue TMA loads.
    {
        float4* z = &ssum4[0][0][0];
        for (int i = tid; i < NWARPS * N_SYSTEMS * 16; i += THREADS)
            z[i] = make_float4(0.f, 0.f, 0.f, 0.f);
        if (tid < NWARPS * N_SYSTEMS) (&scount[0][0])[tid] = 0.0f;
    }
    if (tid == 0) {
        #pragma unroll
        for (int i = 0; i < STAGES; i++) mbar_init(smem_u32(&mbar[i]), 1);
        asm volatile("fence.proxy.async.shared::cta;" ::: "memory");
        #pragma unroll
        for (int i = 0; i < STAGES; i++) {
            long long g = blockIdx.x + (long long)i * gridDim.x;
            if (g < nchunks) {
                uint32_t mb = smem_u32(&mbar[i]);
                mbar_expect_tx(mb, CHUNK_BYTES);
                bulk_ldgsts(smem_u32(&buf[i][0]),
                            (const char*)out + g * CHUNK_BYTES, CHUNK_BYTES, mb);
            }
        }
    }
    __syncthreads();

    // Process one pair. cA/cB = systems of lower/upper row (-1 = invalid).
    auto accum_pair = [&](float4 v, int cA, int cB) {
        const int code = half ? cB : cA;

        float ss = v.x * v.x + v.y * v.y + v.z * v.z + v.w * v.w;
        ss += __shfl_xor_sync(0xFFFFFFFFu, ss, 8);
        ss += __shfl_xor_sync(0xFFFFFFFFu, ss, 4);
        ss += __shfl_xor_sync(0xFFFFFFFFu, ss, 2);
        ss += __shfl_xor_sync(0xFFFFFFFFu, ss, 1);
        const float inv = rsqrtf(fmaxf(ss, 1e-24f));  // == 1/max(||x||,1e-12)

        if (!(cA == cB && cA >= 0)) {
            if (code >= 0) {
                float4 a = ssum4[warp][code][q];
                a.x = fmaf(v.x, inv, a.x);
                a.y = fmaf(v.y, inv, a.y);
                a.z = fmaf(v.z, inv, a.z);
                a.w = fmaf(v.w, inv, a.w);
                ssum4[warp][code][q] = a;
                if (q == 0) scount[warp][code] += 1.0f;  // lanes 0,16 differ
            }
        } else {
            // Rare (~1/16): both rows same system; combine to lower half.
            float4 s;
            s.x = v.x * inv; s.y = v.y * inv; s.z = v.z * inv; s.w = v.w * inv;
            s.x += __shfl_xor_sync(0xFFFFFFFFu, s.x, 16);
            s.y += __shfl_xor_sync(0xFFFFFFFFu, s.y, 16);
            s.z += __shfl_xor_sync(0xFFFFFFFFu, s.z, 16);
            s.w += __shfl_xor_sync(0xFFFFFFFFu, s.w, 16);
            if (half == 0) {
                float4 a = ssum4[warp][code][q];
                a.x += s.x; a.y += s.y; a.z += s.z; a.w += s.w;
                ssum4[warp][code][q] = a;
                if (q == 0) scount[warp][code] += 2.0f;
            }
        }
    };

    // Main pipelined loop.
    int s = 0, phase = 0;
    for (long long g = blockIdx.x; g < nchunks; g += gridDim.x) {
        // System ids for this warp's 8 rows (broadcast; issued before the
        // barrier wait so their latency is hidden by it).
        const int4 sA = __ldg((const int4*)system + g * 8 + warp * 2);
        const int4 sB = __ldg((const int4*)system + g * 8 + warp * 2 + 1);

        mbar_wait(smem_u32(&mbar[s]), phase);

        const float4* bp = (const float4*)buf[s];
        accum_pair(bp[(w8 + 0 + half) * 16 + q], sA.x, sA.y);
        accum_pair(bp[(w8 + 2 + half) * 16 + q], sA.z, sA.w);
        accum_pair(bp[(w8 + 4 + half) * 16 + q], sB.x, sB.y);
        accum_pair(bp[(w8 + 6 + half) * 16 + q], sB.z, sB.w);

        __syncthreads();  // all readers done with buf[s]

        if (tid == 0) {
            long long gn = g + (long long)STAGES * gridDim.x;
            if (gn < nchunks) {
                uint32_t mb = smem_u32(&mbar[s]);
                mbar_expect_tx(mb, CHUNK_BYTES);
                bulk_ldgsts(smem_u32(&buf[s][0]),
                            (const char*)out + gn * CHUNK_BYTES, CHUNK_BYTES, mb);
            }
        }
        s++; if (s == STAGES) { s = 0; phase ^= 1; }
    }

    // Tail rows (n_rows % 32), handled by warp 0 of block 0 from gmem.
    if (blockIdx.x == 0 && warp == 0) {
        const float4* __restrict__ out4 = (const float4*)out;
        for (long long r = nchunks * CHUNK_ROWS; r < (long long)n_rows; r += 2) {
            const long long myrow = r + half;
            float4 v = make_float4(0.f, 0.f, 0.f, 0.f);
            int cA = (int)system[r];
            int cB = (r + 1 < n_rows) ? (int)system[r + 1] : -1;
            if (myrow < n_rows) v = out4[myrow * 16 + q];
            else cA = cA;  // keep shape
            if (myrow >= n_rows) { if (half) cB = -1; }
            accum_pair(v, cA, cB);
        }
    }

    __syncthreads();

    // Block flush: reduce the NWARPS private copies, one global atomic each.
    const float* sf = (const float*)&ssum4[0][0][0];   // [NWARPS][1024]
    for (int i = tid; i < N_SYSTEMS * D; i += THREADS) {
        float acc = 0.0f;
        #pragma unroll
        for (int w = 0; w < NWARPS; w++) acc += sf[w * (N_SYSTEMS * D) + i];
        if (acc != 0.0f) atomicAdd(&g_sums[i], acc);
    }
    if (tid < N_SYSTEMS) {
        float c = 0.0f;
        #pragma unroll
        for (int w = 0; w < NWARPS; w++) c += scount[w][tid];
        if (c != 0.0f) atomicAdd(&g_counts[tid], c);
    }

    // ---- last-block epilogue ----
    __threadfence();
    if (tid == 0) {
        unsigned int v = atomicAdd(&g_ticket, 1u);
        s_last = (v == (unsigned)gridDim.x - 1u) ? 1 : 0;
    }
    __syncthreads();
    if (!s_last) return;

    float* means = (float*)&ssum4[0][0][0];
    for (int i = tid; i < N_SYSTEMS * D; i += THREADS) {
        int sy = i >> 6;            // i / D
        means[i] = g_sums[i] / g_counts[sy];
    }
    __syncthreads();

    // Re-zero scratch for the next call/replay (all reads of g_* done).
    for (int i = tid; i < N_SYSTEMS * D; i += THREADS) g_sums[i] = 0.0f;
    if (tid < N_SYSTEMS) g_counts[tid] = 0.0f;
    if (tid == 0) g_ticket = 0u;

    // 128 threads -> 2 rows of the 16x16 output each.
    for (int pix = tid; pix < N_SYSTEMS * N_SYSTEMS; pix += THREADS) {
        int i = pix >> 4;
        int j = pix & 15;
        float dot = 0.0f;
        #pragma unroll
        for (int d = 0; d < D; d++)
            dot += means[i * D + d] * means[j * D + d];
        float v = 0.5f - 0.5f * dot;
        if (i == j) v = 0.0f;
        dist[pix] = v;
    }
}

extern "C" void kernel_launch(void* const* d_in, const int* in_sizes, int n_in,
                              void* d_out, int out_size) {
    const float* out_mat = (const float*)d_in[0];
    const int* system = (const int*)d_in[1];
    float* dist = (float*)d_out;
    int n_rows = in_sizes[1];  // system has one entry per row

    accumulate_kernel<<<NBLOCKS, THREADS>>>(out_mat, system, dist, n_rows);
}

// round 8
// speedup vs baseline: 1.1868x; 1.1868x over previous
#include <cuda_runtime.h>
#include <cuda_bf16.h>

#define N_SYSTEMS 16
#define D 64
#define NWARPS 8           // warps per block
#define NBLOCKS 888        // 148 SMs * 6 blocks (32.5 KB smem each)

// Global scratch. Zero-initialized at module load; finalize_kernel re-zeroes
// after each use, so the "zero at accumulate-entry" invariant holds across
// graph replays without a dedicated zeroing launch.
__device__ float g_sums[N_SYSTEMS * D];
__device__ float g_counts[N_SYSTEMS];

// Warp processes a QUAD of rows per iteration:
//   pair A: lanes 0-15 -> row 4t,   lanes 16-31 -> row 4t+1
//   pair B: lanes 0-15 -> row 4t+2, lanes 16-31 -> row 4t+3
// Two consecutive LDG.128 warp-instructions = 1024B, fully coalesced.
// CONTIGUOUS partitioning: each CTA owns one contiguous slab of quads and
// its warps sweep it with stride NWARPS (1KB steps) -> DRAM-sequential
// streams per CTA instead of chip-wide 7MB hops.
// Accumulation into per-warp private shared buffers (no atomics).
__global__ void __launch_bounds__(256) accumulate_kernel(
    const float* __restrict__ out, const int* __restrict__ system, int n_rows)
{
    __shared__ float4 ssum4[NWARPS][N_SYSTEMS][16];  // 32 KB
    __shared__ float  scount[NWARPS][N_SYSTEMS];     // 512 B

    const int tid  = threadIdx.x;
    const int lane = tid & 31;
    const int warp = tid >> 5;
    const int half = lane >> 4;      // which row of the pair
    const int q    = lane & 15;      // float4 index within row

    // Zero private accumulators.
    {
        float4* z = &ssum4[0][0][0];
        for (int i = tid; i < NWARPS * N_SYSTEMS * 16; i += 256)
            z[i] = make_float4(0.f, 0.f, 0.f, 0.f);
        if (tid < NWARPS * N_SYSTEMS) (&scount[0][0])[tid] = 0.0f;
    }
    __syncthreads();

    const float4* __restrict__ out4 = (const float4*)out;
    const long long nquads = ((long long)n_rows + 3) >> 2;

    // Contiguous slab for this CTA.
    const long long per_cta = (nquads + gridDim.x - 1) / gridDim.x;
    const long long begin = (long long)blockIdx.x * per_cta;
    const long long end = (begin + per_cta < nquads) ? (begin + per_cta) : nquads;

    // Processes one pair: v = raw float4 chunk, code = sys or -1.
    auto accum_pair = [&](float4 v, int code) {
        // Sum of squares per row: width-16 butterfly (covers both rows).
        float ss = v.x * v.x + v.y * v.y + v.z * v.z + v.w * v.w;
        ss += __shfl_xor_sync(0xFFFFFFFFu, ss, 8);
        ss += __shfl_xor_sync(0xFFFFFFFFu, ss, 4);
        ss += __shfl_xor_sync(0xFFFFFFFFu, ss, 2);
        ss += __shfl_xor_sync(0xFFFFFFFFu, ss, 1);
        float inv = rsqrtf(fmaxf(ss, 1e-24f));   // == 1/max(||x||, 1e-12)

        int other = __shfl_xor_sync(0xFFFFFFFFu, code, 16);
        if (!(code >= 0 && other == code)) {
            // Common path: halves hit distinct systems (or one invalid).
            if (code >= 0) {
                float4 a = ssum4[warp][code][q];
                a.x = fmaf(v.x, inv, a.x);
                a.y = fmaf(v.y, inv, a.y);
                a.z = fmaf(v.z, inv, a.z);
                a.w = fmaf(v.w, inv, a.w);
                ssum4[warp][code][q] = a;
                if (q == 0) scount[warp][code] += 1.0f;  // lanes 0 & 16 differ
            }
        } else {
            // Rare path (~1/16): both halves same system; combine to lower.
            float4 s;
            s.x = v.x * inv; s.y = v.y * inv; s.z = v.z * inv; s.w = v.w * inv;
            s.x += __shfl_xor_sync(0xFFFFFFFFu, s.x, 16);
            s.y += __shfl_xor_sync(0xFFFFFFFFu, s.y, 16);
            s.z += __shfl_xor_sync(0xFFFFFFFFu, s.z, 16);
            s.w += __shfl_xor_sync(0xFFFFFFFFu, s.w, 16);
            if (half == 0) {
                float4 a = ssum4[warp][code][q];
                a.x += s.x; a.y += s.y; a.z += s.z; a.w += s.w;
                ssum4[warp][code][q] = a;
                if (q == 0) scount[warp][code] += 2.0f;
            }
        }
    };

    // Fetch quad tt.
    auto fetch = [&](long long tt, float4& va, float4& vb, int& ca, int& cb) {
        va = make_float4(0.f, 0.f, 0.f, 0.f);
        vb = va; ca = -1; cb = -1;
        long long rowA = 4 * tt + half;
        long long rowB = rowA + 2;
        if (rowA < n_rows) {
            va = out4[tt * 64 + lane];
            ca = system[rowA];
        }
        if (rowB < n_rows) {
            vb = out4[tt * 64 + 32 + lane];
            cb = system[rowB];
        }
    };

    long long t = begin + warp;
    float4 va, vb; int ca, cb;
    if (t < end) fetch(t, va, vb, ca, cb);

    while (t < end) {
        long long tn = t + NWARPS;
        float4 van, vbn; int can, cbn;
        if (tn < end) fetch(tn, van, vbn, can, cbn);

        accum_pair(va, ca);
        accum_pair(vb, cb);

        va = van; vb = vbn; ca = can; cb = cbn; t = tn;
    }

    __syncthreads();

    // Block flush: reduce the NWARPS private copies, one global atomic each.
    const float* sf = (const float*)&ssum4[0][0][0];   // [NWARPS][1024]
    for (int i = tid; i < N_SYSTEMS * D; i += 256) {
        float acc = 0.0f;
        #pragma unroll
        for (int w = 0; w < NWARPS; w++) acc += sf[w * (N_SYSTEMS * D) + i];
        if (acc != 0.0f) atomicAdd(&g_sums[i], acc);
    }
    if (tid < N_SYSTEMS) {
        float c = 0.0f;
        #pragma unroll
        for (int w = 0; w < NWARPS; w++) c += scount[w][tid];
        if (c != 0.0f) atomicAdd(&g_counts[tid], c);
    }
}

// Single-block epilogue: means -> Gram -> distance matrix, then re-zero
// the global scratch for the next call/replay.
__global__ void __launch_bounds__(256) finalize_kernel(float* __restrict__ dist)
{
    __shared__ float means[N_SYSTEMS * D];
    int t = threadIdx.x;

    for (int i = t; i < N_SYSTEMS * D; i += 256) {
        int s = i / D;
        means[i] = g_sums[i] / g_counts[s];
    }
    __syncthreads();

    // Re-zero scratch (all reads of g_* are done).
    for (int i = t; i < N_SYSTEMS * D; i += 256) g_sums[i] = 0.0f;
    if (t < N_SYSTEMS) g_counts[t] = 0.0f;

    int i = t >> 4;
    int j = t & 15;
    float dot = 0.0f;
    #pragma unroll
    for (int d = 0; d < D; d++)
        dot += means[i * D + d] * means[j * D + d];

    float v = 0.5f - 0.5f * dot;
    if (i == j) v = 0.0f;
    dist[i * N_SYSTEMS + j] = v;
}

extern "C" void kernel_launch(void* const* d_in, const int* in_sizes, int n_in,
                              void* d_out, int out_size) {
    const float* out_mat = (const float*)d_in[0];
    const int* system = (const int*)d_in[1];
    float* dist = (float*)d_out;
    int n_rows = in_sizes[1];  // system has one entry per row

    accumulate_kernel<<<NBLOCKS, 256>>>(out_mat, system, n_rows);
    finalize_kernel<<<1, 256>>>(dist);
}

// round 9
// speedup vs baseline: 1.3271x; 1.1182x over previous
#include <cuda_runtime.h>
#include <cuda_bf16.h>

#define N_SYSTEMS 16
#define D 64
#define NWARPS 8           // warps per block
#define NBLOCKS 888        // 148 SMs * 6 blocks (32.5 KB smem each)

// Global scratch. Zero-initialized at module load; finalize_kernel re-zeroes
// after each use, so the "zero at accumulate-entry" invariant holds across
// graph replays without a dedicated zeroing launch.
__device__ float g_sums[N_SYSTEMS * D];
__device__ float g_counts[N_SYSTEMS];

// Warp processes a PAIR of rows per iteration:
//   lanes 0-15  -> row 2p   (float4 chunk lane)
//   lanes 16-31 -> row 2p+1 (float4 chunk lane-16)
// One LDG.128 warp-instruction = 512B = both rows, fully coalesced.
// Both system codes come from one broadcast int2 load (no cross-half SHFL).
// Accumulation into per-warp private shared buffers (no atomics).
__global__ void __launch_bounds__(256) accumulate_kernel(
    const float* __restrict__ out, const int* __restrict__ system, int n_rows)
{
    __shared__ float4 ssum4[NWARPS][N_SYSTEMS][16];  // 32 KB
    __shared__ float  scount[NWARPS][N_SYSTEMS];     // 512 B

    const int tid  = threadIdx.x;
    const int lane = tid & 31;
    const int warp = tid >> 5;
    const int half = lane >> 4;      // 0 = row 2p, 1 = row 2p+1
    const int q    = lane & 15;      // float4 index within row

    // Zero private accumulators.
    {
        float4* z = &ssum4[0][0][0];
        for (int i = tid; i < NWARPS * N_SYSTEMS * 16; i += 256)
            z[i] = make_float4(0.f, 0.f, 0.f, 0.f);
        if (tid < NWARPS * N_SYSTEMS) (&scount[0][0])[tid] = 0.0f;
    }
    __syncthreads();

    const float4* __restrict__ out4 = (const float4*)out;
    const long long npairs = (long long)(n_rows + 1) >> 1;
    const long long total_warps = (long long)gridDim.x * NWARPS;
    long long p = (long long)blockIdx.x * NWARPS + warp;

    // Prefetch first pair.
    float4 v = make_float4(0.f, 0.f, 0.f, 0.f);
    int cA = -1, cB = -1;
    if (p < npairs) {
        v = __ldcs(&out4[p * 32 + lane]);
        int2 c = __ldg((const int2*)system + p);   // broadcast: both codes
        cA = c.x;
        cB = (2 * p + 1 < (long long)n_rows) ? c.y : -1;
    }

    while (p < npairs) {
        // Prefetch next pair.
        long long pn = p + total_warps;
        float4 vn = make_float4(0.f, 0.f, 0.f, 0.f);
        int cAn = -1, cBn = -1;
        if (pn < npairs) {
            vn = __ldcs(&out4[pn * 32 + lane]);
            int2 c = __ldg((const int2*)system + pn);
            cAn = c.x;
            cBn = (2 * pn + 1 < (long long)n_rows) ? c.y : -1;
        }

        // ---- process current pair ----
        const int code = half ? cB : cA;

        // Sum of squares per row: width-16 butterfly (covers both rows).
        float ss = v.x * v.x + v.y * v.y + v.z * v.z + v.w * v.w;
        ss += __shfl_xor_sync(0xFFFFFFFFu, ss, 8);
        ss += __shfl_xor_sync(0xFFFFFFFFu, ss, 4);
        ss += __shfl_xor_sync(0xFFFFFFFFu, ss, 2);
        ss += __shfl_xor_sync(0xFFFFFFFFu, ss, 1);
        const float inv = rsqrtf(fmaxf(ss, 1e-24f)); // == 1/max(||x||,1e-12)

        if (!(cA == cB && cA >= 0)) {
            // Common path: halves hit distinct systems (or one invalid).
            if (code >= 0) {
                float4 a = ssum4[warp][code][q];
                a.x = fmaf(v.x, inv, a.x);
                a.y = fmaf(v.y, inv, a.y);
                a.z = fmaf(v.z, inv, a.z);
                a.w = fmaf(v.w, inv, a.w);
                ssum4[warp][code][q] = a;
                if (q == 0) scount[warp][code] += 1.0f;  // lanes 0,16 differ
            }
        } else {
            // Rare path (~1/16): both halves same system; combine to lower.
            float4 s;
            s.x = v.x * inv; s.y = v.y * inv; s.z = v.z * inv; s.w = v.w * inv;
            s.x += __shfl_xor_sync(0xFFFFFFFFu, s.x, 16);
            s.y += __shfl_xor_sync(0xFFFFFFFFu, s.y, 16);
            s.z += __shfl_xor_sync(0xFFFFFFFFu, s.z, 16);
            s.w += __shfl_xor_sync(0xFFFFFFFFu, s.w, 16);
            if (half == 0) {
                float4 a = ssum4[warp][code][q];
                a.x += s.x; a.y += s.y; a.z += s.z; a.w += s.w;
                ssum4[warp][code][q] = a;
                if (q == 0) scount[warp][code] += 2.0f;
            }
        }

        v = vn; cA = cAn; cB = cBn; p = pn;
    }

    __syncthreads();

    // Block flush: reduce the NWARPS private copies, one global atomic each.
    const float* sf = (const float*)&ssum4[0][0][0];   // [NWARPS][1024]
    for (int i = tid; i < N_SYSTEMS * D; i += 256) {
        float acc = 0.0f;
        #pragma unroll
        for (int w = 0; w < NWARPS; w++) acc += sf[w * (N_SYSTEMS * D) + i];
        if (acc != 0.0f) atomicAdd(&g_sums[i], acc);
    }
    if (tid < N_SYSTEMS) {
        float c = 0.0f;
        #pragma unroll
        for (int w = 0; w < NWARPS; w++) c += scount[w][tid];
        if (c != 0.0f) atomicAdd(&g_counts[tid], c);
    }
}

// Single-block epilogue: means -> Gram -> distance matrix, then re-zero
// the global scratch for the next call/replay.
__global__ void __launch_bounds__(256) finalize_kernel(float* __restrict__ dist)
{
    __shared__ float means[N_SYSTEMS * D];
    int t = threadIdx.x;

    for (int i = t; i < N_SYSTEMS * D; i += 256) {
        int s = i / D;
        means[i] = g_sums[i] / g_counts[s];
    }
    __syncthreads();

    // Re-zero scratch (all reads of g_* are done).
    for (int i = t; i < N_SYSTEMS * D; i += 256) g_sums[i] = 0.0f;
    if (t < N_SYSTEMS) g_counts[t] = 0.0f;

    int i = t >> 4;
    int j = t & 15;
    float dot = 0.0f;
    #pragma unroll
    for (int d = 0; d < D; d++)
        dot += means[i * D + d] * means[j * D + d];

    float v = 0.5f - 0.5f * dot;
    if (i == j) v = 0.0f;
    dist[i * N_SYSTEMS + j] = v;
}

extern "C" void kernel_launch(void* const* d_in, const int* in_sizes, int n_in,
                              void* d_out, int out_size) {
    const float* out_mat = (const float*)d_in[0];
    const int* system = (const int*)d_in[1];
    float* dist = (float*)d_out;
    int n_rows = in_sizes[1];  // system has one entry per row

    accumulate_kernel<<<NBLOCKS, 256>>>(out_mat, system, n_rows);
    finalize_kernel<<<1, 256>>>(dist);
}